// round 4
// baseline (speedup 1.0000x reference)
#include <cuda_runtime.h>
#include <math.h>

#define EPSV 1e-5f

#define B_   2
#define C_   512
#define H_   128
#define W_   256
#define NPIX (H_*W_)        // 32768
#define CK_  256
#define KP_  19
#define CO_  512
#define IC2  (2*C_)         // 1024
#define KCONV (IC2*9)       // 9216

// Scratch (device globals; no allocation allowed)
__device__ float g_q1 [B_*CK_*NPIX];
__device__ float g_q  [B_*CK_*NPIX];
__device__ float g_k1 [B_*CK_*KP_];
__device__ float g_k  [B_*CK_*KP_];
__device__ float g_v  [B_*CK_*KP_];
__device__ float g_ctx[B_*CK_*NPIX];
__device__ float g_ctxo[B_*C_*NPIX];

// ---------------------------------------------------------------------------
// Fused GEMM + BN + ReLU:  Y[b][m][n] = relu(bn_m( sum_k W[m][k] * X[b][k][n] ))
// W: (M,K) row-major. X: batch-strided (K,N). Y: batch-strided (M,N).
// bn: (4,M) rows = gamma, beta, mean, var.
// Block: 256 threads, tile 128x128, BK=8, 8x8 per thread.
// ---------------------------------------------------------------------------
__global__ void __launch_bounds__(256)
gemm_bn_relu_k(const float* __restrict__ Wm, const float* __restrict__ Xg,
               const float* __restrict__ bn, float* __restrict__ Yg,
               int M, int K, int N)
{
    const int b = blockIdx.z;
    const float* X = Xg + (size_t)b * K * N;
    float*       Y = Yg + (size_t)b * M * N;

    __shared__ float As[8][128];
    __shared__ float Bs[8][128];

    const int m0 = blockIdx.y * 128;
    const int n0 = blockIdx.x * 128;
    const int tid = threadIdx.x;
    const int tx = tid & 15;     // 0..15 -> n
    const int ty = tid >> 4;     // 0..15 -> m

    float acc[8][8];
    #pragma unroll
    for (int i = 0; i < 8; i++)
        #pragma unroll
        for (int j = 0; j < 8; j++) acc[i][j] = 0.f;

    for (int k0 = 0; k0 < K; k0 += 8) {
        // A tile: 128 rows x 8 k. thread -> row=tid/2, kq=(tid&1)*4
        {
            int row = tid >> 1;
            int kq  = (tid & 1) * 4;
            int m   = m0 + row;
            float4 a = make_float4(0.f, 0.f, 0.f, 0.f);
            if (m < M) a = *(const float4*)&Wm[(size_t)m * K + k0 + kq];
            As[kq+0][row] = a.x; As[kq+1][row] = a.y;
            As[kq+2][row] = a.z; As[kq+3][row] = a.w;
        }
        // B tile: 8 k-rows x 128 n. thread -> krow=tid/32, nq=(tid&31)*4
        // float4 path only when N is a multiple of 4 (else row offsets are
        // not 16B-aligned -> misaligned-address trap; e.g. the N=19 GEMMs).
        {
            int krow = tid >> 5;
            int nq   = (tid & 31) * 4;
            int n    = n0 + nq;
            float4 v;
            if (((N & 3) == 0) && (n + 3 < N)) {
                v = *(const float4*)&X[(size_t)(k0 + krow) * N + n];
            } else {
                float t0 = (n+0 < N) ? X[(size_t)(k0+krow)*N + n+0] : 0.f;
                float t1 = (n+1 < N) ? X[(size_t)(k0+krow)*N + n+1] : 0.f;
                float t2 = (n+2 < N) ? X[(size_t)(k0+krow)*N + n+2] : 0.f;
                float t3 = (n+3 < N) ? X[(size_t)(k0+krow)*N + n+3] : 0.f;
                v = make_float4(t0, t1, t2, t3);
            }
            *(float4*)&Bs[krow][nq] = v;
        }
        __syncthreads();
        #pragma unroll
        for (int kk = 0; kk < 8; kk++) {
            float a[8], bf[8];
            *(float4*)&a[0]  = *(const float4*)&As[kk][ty*8];
            *(float4*)&a[4]  = *(const float4*)&As[kk][ty*8 + 4];
            *(float4*)&bf[0] = *(const float4*)&Bs[kk][tx*8];
            *(float4*)&bf[4] = *(const float4*)&Bs[kk][tx*8 + 4];
            #pragma unroll
            for (int i = 0; i < 8; i++)
                #pragma unroll
                for (int j = 0; j < 8; j++)
                    acc[i][j] += a[i] * bf[j];
        }
        __syncthreads();
    }

    #pragma unroll
    for (int i = 0; i < 8; i++) {
        int m = m0 + ty*8 + i;
        if (m >= M) continue;
        float sc = bn[m] * rsqrtf(bn[3*M + m] + EPSV);
        float sh = bn[M + m] - bn[2*M + m] * sc;
        #pragma unroll
        for (int j = 0; j < 8; j++) {
            int n = n0 + tx*8 + j;
            if (n < N) {
                float v = acc[i][j] * sc + sh;
                Y[(size_t)m * N + n] = v > 0.f ? v : 0.f;
            }
        }
    }
}

// ---------------------------------------------------------------------------
// Attention: per pixel n:  sim_k = (1/16) * sum_c q[c,n]*k[c,t]; softmax over t;
//            ctx[c,n] = sum_t sim_t * v[c,t].  4 pixels per thread.
// ---------------------------------------------------------------------------
__global__ void __launch_bounds__(256)
attn_k(const float* __restrict__ q, const float* __restrict__ kmat,
       const float* __restrict__ vmat, float* __restrict__ ctx)
{
    const int b  = blockIdx.y;
    const int n0 = blockIdx.x * 1024 + threadIdx.x * 4;

    __shared__ float ksh[CK_*KP_];
    __shared__ float vsh[CK_*KP_];
    for (int i = threadIdx.x; i < CK_*KP_; i += 256) {
        ksh[i] = kmat[b*CK_*KP_ + i];
        vsh[i] = vmat[b*CK_*KP_ + i];
    }
    __syncthreads();

    float sim[4][KP_];
    #pragma unroll
    for (int p = 0; p < 4; p++)
        #pragma unroll
        for (int t = 0; t < KP_; t++) sim[p][t] = 0.f;

    const float* qb = q + (size_t)b * CK_ * NPIX;
    for (int c = 0; c < CK_; c++) {
        float4 qv = *(const float4*)&qb[(size_t)c * NPIX + n0];
        #pragma unroll
        for (int t = 0; t < KP_; t++) {
            float kv = ksh[c*KP_ + t];
            sim[0][t] += qv.x * kv;
            sim[1][t] += qv.y * kv;
            sim[2][t] += qv.z * kv;
            sim[3][t] += qv.w * kv;
        }
    }

    #pragma unroll
    for (int p = 0; p < 4; p++) {
        float mx = -1e30f;
        #pragma unroll
        for (int t = 0; t < KP_; t++) { sim[p][t] *= 0.0625f; mx = fmaxf(mx, sim[p][t]); }
        float s = 0.f;
        #pragma unroll
        for (int t = 0; t < KP_; t++) { float e = __expf(sim[p][t] - mx); sim[p][t] = e; s += e; }
        float inv = 1.f / s;
        #pragma unroll
        for (int t = 0; t < KP_; t++) sim[p][t] *= inv;
    }

    float* cb = ctx + (size_t)b * CK_ * NPIX;
    for (int c = 0; c < CK_; c++) {
        float a0 = 0.f, a1 = 0.f, a2 = 0.f, a3 = 0.f;
        #pragma unroll
        for (int t = 0; t < KP_; t++) {
            float vv = vsh[c*KP_ + t];
            a0 += sim[0][t] * vv;
            a1 += sim[1][t] * vv;
            a2 += sim[2][t] * vv;
            a3 += sim[3][t] * vv;
        }
        *(float4*)&cb[(size_t)c * NPIX + n0] = make_float4(a0, a1, a2, a3);
    }
}

// ---------------------------------------------------------------------------
// 3x3 conv over virtual concat [ctxo ; x] (1024 in ch) -> 512 out ch,
// SAME padding, fused BN+ReLU. Implicit GEMM: M=512, K=9216, N=32768.
// ---------------------------------------------------------------------------
__global__ void __launch_bounds__(256)
conv3x3_bn_relu_k(const float* __restrict__ Wm,    // (512, 9216)
                  const float* __restrict__ ctxo,  // (B,512,H,W)
                  const float* __restrict__ xin,   // (B,512,H,W)
                  const float* __restrict__ bn,    // (4,512)
                  float* __restrict__ Yg)          // (B,512,H,W)
{
    const int b = blockIdx.z;
    float* Y = Yg + (size_t)b * CO_ * NPIX;

    __shared__ float As[8][128];
    __shared__ float Bs[8][128];

    const int m0 = blockIdx.y * 128;
    const int n0 = blockIdx.x * 128;
    const int tid = threadIdx.x;
    const int tx = tid & 15;
    const int ty = tid >> 4;

    float acc[8][8];
    #pragma unroll
    for (int i = 0; i < 8; i++)
        #pragma unroll
        for (int j = 0; j < 8; j++) acc[i][j] = 0.f;

    const float* ctxb = ctxo + (size_t)b * C_ * NPIX;
    const float* xb   = xin  + (size_t)b * C_ * NPIX;

    for (int k0 = 0; k0 < KCONV; k0 += 8) {
        // A tile: weights, contiguous in K (KCONV multiple of 4 -> aligned)
        {
            int row = tid >> 1;
            int kq  = (tid & 1) * 4;
            float4 a = *(const float4*)&Wm[(size_t)(m0 + row) * KCONV + k0 + kq];
            As[kq+0][row] = a.x; As[kq+1][row] = a.y;
            As[kq+2][row] = a.z; As[kq+3][row] = a.w;
        }
        // B tile: implicit im2col
        {
            int krow = tid >> 5;
            int nqb  = (tid & 31) * 4;
            int kg   = k0 + krow;
            int ic   = kg / 9;
            int tap  = kg - ic * 9;
            int ky   = tap / 3 - 1;
            int kx   = tap - (tap / 3) * 3 - 1;
            const float* src = (ic < C_) ? (ctxb + (size_t)ic * NPIX)
                                         : (xb   + (size_t)(ic - C_) * NPIX);
            #pragma unroll
            for (int j = 0; j < 4; j++) {
                int n  = n0 + nqb + j;
                int y  = n >> 8;          // W_ = 256
                int x  = n & 255;
                int yy = y + ky;
                int xx = x + kx;
                float v = 0.f;
                if (yy >= 0 && yy < H_ && xx >= 0 && xx < W_)
                    v = src[yy * W_ + xx];
                Bs[krow][nqb + j] = v;
            }
        }
        __syncthreads();
        #pragma unroll
        for (int kk = 0; kk < 8; kk++) {
            float a[8], bf[8];
            *(float4*)&a[0]  = *(const float4*)&As[kk][ty*8];
            *(float4*)&a[4]  = *(const float4*)&As[kk][ty*8 + 4];
            *(float4*)&bf[0] = *(const float4*)&Bs[kk][tx*8];
            *(float4*)&bf[4] = *(const float4*)&Bs[kk][tx*8 + 4];
            #pragma unroll
            for (int i = 0; i < 8; i++)
                #pragma unroll
                for (int j = 0; j < 8; j++)
                    acc[i][j] += a[i] * bf[j];
        }
        __syncthreads();
    }

    #pragma unroll
    for (int i = 0; i < 8; i++) {
        int m = m0 + ty*8 + i;
        float sc = bn[m] * rsqrtf(bn[3*CO_ + m] + EPSV);
        float sh = bn[CO_ + m] - bn[2*CO_ + m] * sc;
        #pragma unroll
        for (int j = 0; j < 8; j++) {
            int n = n0 + tx*8 + j;
            float v = acc[i][j] * sc + sh;
            Y[(size_t)m * NPIX + n] = v > 0.f ? v : 0.f;
        }
    }
}

// ---------------------------------------------------------------------------
extern "C" void kernel_launch(void* const* d_in, const int* in_sizes, int n_in,
                              void* d_out, int out_size)
{
    const float *x, *proxy, *wq1, *wq2, *wk1, *wk2, *wv, *wout, *wbot;
    const float *bnq1, *bnq2, *bnk1, *bnk2, *bnv, *bnout, *bnbot;

    x     = (const float*)d_in[0];
    proxy = (const float*)d_in[1];
    if (in_sizes[3] == 1024 || in_sizes[3] == 2048) {
        // dict order: w/bn interleaved
        wq1  = (const float*)d_in[2];  bnq1  = (const float*)d_in[3];
        wq2  = (const float*)d_in[4];  bnq2  = (const float*)d_in[5];
        wk1  = (const float*)d_in[6];  bnk1  = (const float*)d_in[7];
        wk2  = (const float*)d_in[8];  bnk2  = (const float*)d_in[9];
        wv   = (const float*)d_in[10]; bnv   = (const float*)d_in[11];
        wout = (const float*)d_in[12]; bnout = (const float*)d_in[13];
        wbot = (const float*)d_in[14]; bnbot = (const float*)d_in[15];
    } else {
        // signature order: all weights, then all bns
        wq1  = (const float*)d_in[2];
        wq2  = (const float*)d_in[3];
        wk1  = (const float*)d_in[4];
        wk2  = (const float*)d_in[5];
        wv   = (const float*)d_in[6];
        wout = (const float*)d_in[7];
        wbot = (const float*)d_in[8];
        bnq1  = (const float*)d_in[9];
        bnq2  = (const float*)d_in[10];
        bnk1  = (const float*)d_in[11];
        bnk2  = (const float*)d_in[12];
        bnv   = (const float*)d_in[13];
        bnout = (const float*)d_in[14];
        bnbot = (const float*)d_in[15];
    }

    float *pq1, *pq, *pk1, *pk, *pv, *pctx, *pctxo;
    cudaGetSymbolAddress((void**)&pq1,  g_q1);
    cudaGetSymbolAddress((void**)&pq,   g_q);
    cudaGetSymbolAddress((void**)&pk1,  g_k1);
    cudaGetSymbolAddress((void**)&pk,   g_k);
    cudaGetSymbolAddress((void**)&pv,   g_v);
    cudaGetSymbolAddress((void**)&pctx, g_ctx);
    cudaGetSymbolAddress((void**)&pctxo, g_ctxo);

    float* out = (float*)d_out;

    // q path: (B,512,HW) -> (B,256,HW) -> (B,256,HW)
    gemm_bn_relu_k<<<dim3(NPIX/128, 2, B_), 256>>>(wq1, x,   bnq1, pq1, CK_, C_,  NPIX);
    gemm_bn_relu_k<<<dim3(NPIX/128, 2, B_), 256>>>(wq2, pq1, bnq2, pq,  CK_, CK_, NPIX);

    // k path: (B,512,19) -> (B,256,19) -> (B,256,19) ; v: (B,512,19) -> (B,256,19)
    gemm_bn_relu_k<<<dim3(1, 2, B_), 256>>>(wk1, proxy, bnk1, pk1, CK_, C_,  KP_);
    gemm_bn_relu_k<<<dim3(1, 2, B_), 256>>>(wk2, pk1,   bnk2, pk,  CK_, CK_, KP_);
    gemm_bn_relu_k<<<dim3(1, 2, B_), 256>>>(wv,  proxy, bnv,  pv,  CK_, C_,  KP_);

    // attention -> ctx (B,256,HW)
    attn_k<<<dim3(NPIX/1024, B_), 256>>>(pq, pk, pv, pctx);

    // wout: (B,256,HW) -> (B,512,HW)
    gemm_bn_relu_k<<<dim3(NPIX/128, 4, B_), 256>>>(wout, pctx, bnout, pctxo, C_, CK_, NPIX);

    // 3x3 conv over [ctxo ; x] -> output
    conv3x3_bn_relu_k<<<dim3(NPIX/128, CO_/128, B_), 256>>>(wbot, pctxo, x, bnbot, out);
}

// round 6
// speedup vs baseline: 2.4022x; 2.4022x over previous
#include <cuda_runtime.h>
#include <math.h>
#include <stdint.h>

#define EPSV 1e-5f

#define B_   2
#define C_   512
#define H_   128
#define W_   256
#define NPIX (H_*W_)        // 32768
#define CK_  256
#define KP_  19
#define CO_  512
#define KCONV (1024*9)      // 9216

// ---------------- scratch (device globals; no allocation allowed) ----------
__device__ float g_q1  [B_*CK_*NPIX];
__device__ float g_q   [B_*CK_*NPIX];
__device__ float g_k1  [B_*CK_*KP_];
__device__ float g_k   [B_*CK_*KP_];
__device__ float g_v   [B_*CK_*KP_];
__device__ float g_ctx [B_*CK_*NPIX];
__device__ float g_ctxo[B_*C_*NPIX];
__device__ float g_xr  [B_*C_*NPIX];     // x rounded to tf32
__device__ float g_wq1r [CK_*C_];
__device__ float g_wq2r [CK_*CK_];
__device__ float g_woutr[C_*CK_];
__device__ float g_wbotr[CO_*KCONV];

// ---------------- helpers --------------------------------------------------
__device__ __forceinline__ float to_tf32(float x) {
    uint32_t r; asm("cvt.rna.tf32.f32 %0, %1;" : "=r"(r) : "f"(x));
    return __uint_as_float(r);
}
__device__ __forceinline__ void cp4(uint32_t dst, const void* src) {
    asm volatile("cp.async.ca.shared.global [%0], [%1], 4;\n" :: "r"(dst), "l"(src));
}
__device__ __forceinline__ uint32_t saddr(const void* p) {
    return (uint32_t)__cvta_generic_to_shared(p);
}
__device__ __forceinline__ void mma_tf32(float* d, const uint32_t* a, const uint32_t* b) {
    asm volatile(
        "mma.sync.aligned.m16n8k8.row.col.f32.tf32.tf32.f32 "
        "{%0,%1,%2,%3}, {%4,%5,%6,%7}, {%8,%9}, {%0,%1,%2,%3};\n"
        : "+f"(d[0]), "+f"(d[1]), "+f"(d[2]), "+f"(d[3])
        : "r"(a[0]), "r"(a[1]), "r"(a[2]), "r"(a[3]), "r"(b[0]), "r"(b[1]));
}

// round-to-tf32 prepass (float4 vectorized; n divisible by 4)
__global__ void round_k(const float* __restrict__ s, float* __restrict__ d, int n4) {
    int i = blockIdx.x * 256 + threadIdx.x;
    if (i < n4) {
        float4 v = ((const float4*)s)[i];
        v.x = to_tf32(v.x); v.y = to_tf32(v.y); v.z = to_tf32(v.z); v.w = to_tf32(v.w);
        ((float4*)d)[i] = v;
    }
}

// ---------------------------------------------------------------------------
// tf32 tensor-core GEMM / implicit-conv kernel.
//   Y[b](M, NPIX) = relu(bn( A(M,K) * B[b](K, NPIX) ))
// CONV=true: B is implicit im2col of [Xg(ctxo) ; X2g(x)] with 3x3 SAME taps.
// Block 128x128, 256 thr (8 warps, warp tile 64x32), BK=16, 2-stage cp.async.
// SMEM layout: As/Bs[stage][row 0..127][24], k in 0..15 stored at
//   pos(k) = (k>>3)*8 + (k&3)*2 + ((k>>2)&1)   (makes every frag one LDS.64)
// ---------------------------------------------------------------------------
template<bool CONV>
__global__ void __launch_bounds__(256, 2)
mma_gemm_k(const float* __restrict__ Aw, const float* __restrict__ Xg,
           const float* __restrict__ X2g, const float* __restrict__ bn,
           float* __restrict__ Yg, int K, int Mtot, int round_out)
{
    __shared__ float As[2][128][24];
    __shared__ float Bs[2][128][24];

    const int b    = blockIdx.z;
    const int m0   = blockIdx.y * 128;
    const int n0   = blockIdx.x * 128;
    const int tid  = threadIdx.x;
    const int lane = tid & 31;
    const int wid  = tid >> 5;
    const int wm   = wid & 1;   // 2 warps along M
    const int wn   = wid >> 1;  // 4 warps along N

    const float* Xb  = CONV ? (Xg  + (size_t)b * C_ * NPIX) : (Xg + (size_t)b * K * NPIX);
    const float* X2b = CONV ? (X2g + (size_t)b * C_ * NPIX) : nullptr;
    float*       Yb  = Yg + (size_t)b * Mtot * NPIX;

    float acc[4][4][4];
    #pragma unroll
    for (int i = 0; i < 4; i++)
        #pragma unroll
        for (int j = 0; j < 4; j++)
            #pragma unroll
            for (int r = 0; r < 4; r++) acc[i][j][r] = 0.f;

    const int nkb = K / 16;

    auto stage = [&](int st, int kb) {
        const int k0 = kb * 16;
        // ---- A tile: 128 rows x 16 k. thread: kk = tid&15, m = (tid>>4)+16p.
        {
            int kk   = tid & 15;
            int posk = ((kk >> 3) << 3) + ((kk & 3) << 1) + ((kk >> 2) & 1);
            #pragma unroll
            for (int p = 0; p < 8; p++) {
                int m = (tid >> 4) + p * 16;
                cp4(saddr(&As[st][m][posk]), &Aw[(size_t)(m0 + m) * K + k0 + kk]);
            }
        }
        // ---- B tile: 16 krows x 128 n. thread: krow = (tid>>5)+8*pass, n=(tid&31)+32j.
        #pragma unroll
        for (int pass = 0; pass < 2; pass++) {
            int krow = (tid >> 5) + pass * 8;
            int posr = ((krow >> 3) << 3) + ((krow & 3) << 1) + ((krow >> 2) & 1);
            if (CONV) {
                int kg  = k0 + krow;
                int ic  = kg / 9;
                int tap = kg - ic * 9;
                int ky  = tap / 3 - 1;
                int kx  = tap - (tap / 3) * 3 - 1;
                const float* src = (ic < C_) ? (Xb + (size_t)ic * NPIX)
                                             : (X2b + (size_t)(ic - C_) * NPIX);
                #pragma unroll
                for (int j = 0; j < 4; j++) {
                    int n  = (tid & 31) + 32 * j;
                    int np = n0 + n;
                    int yy = (np >> 8) + ky;
                    int xx = (np & 255) + kx;
                    if (yy >= 0 && yy < H_ && xx >= 0 && xx < W_)
                        cp4(saddr(&Bs[st][n][posr]), &src[yy * W_ + xx]);
                    else
                        Bs[st][n][posr] = 0.f;
                }
            } else {
                const float* src = Xb + (size_t)(k0 + krow) * NPIX + n0;
                #pragma unroll
                for (int j = 0; j < 4; j++) {
                    int n = (tid & 31) + 32 * j;
                    cp4(saddr(&Bs[st][n][posr]), &src[n]);
                }
            }
        }
    };

    auto domma = [&](int st) {
        #pragma unroll
        for (int s = 0; s < 2; s++) {
            const int co = s * 8 + ((lane & 3) << 1);
            uint32_t a[4][4], bb[4][2];
            #pragma unroll
            for (int mt = 0; mt < 4; mt++) {
                int r = wm * 64 + mt * 16 + (lane >> 2);
                float2 t0 = *(const float2*)&As[st][r][co];
                float2 t1 = *(const float2*)&As[st][r + 8][co];
                a[mt][0] = __float_as_uint(t0.x);  // (row, c)
                a[mt][2] = __float_as_uint(t0.y);  // (row, c+4)
                a[mt][1] = __float_as_uint(t1.x);  // (row+8, c)
                a[mt][3] = __float_as_uint(t1.y);  // (row+8, c+4)
            }
            #pragma unroll
            for (int nt = 0; nt < 4; nt++) {
                int n = wn * 32 + nt * 8 + (lane >> 2);
                float2 t = *(const float2*)&Bs[st][n][co];
                bb[nt][0] = __float_as_uint(t.x);  // (k=c,   n)
                bb[nt][1] = __float_as_uint(t.y);  // (k=c+4, n)
            }
            #pragma unroll
            for (int mt = 0; mt < 4; mt++)
                #pragma unroll
                for (int nt = 0; nt < 4; nt++)
                    mma_tf32(acc[mt][nt], a[mt], bb[nt]);
        }
    };

    stage(0, 0);
    asm volatile("cp.async.commit_group;\n");

    for (int kb = 0; kb < nkb; kb++) {
        if (kb + 1 < nkb) {
            stage((kb + 1) & 1, kb + 1);
            asm volatile("cp.async.commit_group;\n");
            asm volatile("cp.async.wait_group 1;\n");
        } else {
            asm volatile("cp.async.wait_group 0;\n");
        }
        __syncthreads();
        domma(kb & 1);
        __syncthreads();
    }

    // epilogue: BN + ReLU (+ optional tf32 rounding), float2 stores
    #pragma unroll
    for (int mt = 0; mt < 4; mt++) {
        int mr = m0 + wm * 64 + mt * 16 + (lane >> 2);
        #pragma unroll
        for (int half = 0; half < 2; half++) {
            int m = mr + half * 8;
            float sc = bn[m] * rsqrtf(bn[3 * Mtot + m] + EPSV);
            float sh = bn[Mtot + m] - bn[2 * Mtot + m] * sc;
            #pragma unroll
            for (int nt = 0; nt < 4; nt++) {
                int n = n0 + wn * 32 + nt * 8 + ((lane & 3) << 1);
                float v0 = acc[mt][nt][half * 2 + 0] * sc + sh;
                float v1 = acc[mt][nt][half * 2 + 1] * sc + sh;
                v0 = v0 > 0.f ? v0 : 0.f;
                v1 = v1 > 0.f ? v1 : 0.f;
                if (round_out) { v0 = to_tf32(v0); v1 = to_tf32(v1); }
                *(float2*)&Yb[(size_t)m * NPIX + n] = make_float2(v0, v1);
            }
        }
    }
}

// ---------------------------------------------------------------------------
// fp32 GEMM+BN+ReLU (kept for the tiny N=19 k/v-path GEMMs)
// ---------------------------------------------------------------------------
__global__ void __launch_bounds__(256)
gemm_bn_relu_k(const float* __restrict__ Wm, const float* __restrict__ Xg,
               const float* __restrict__ bn, float* __restrict__ Yg,
               int M, int K, int N)
{
    const int b = blockIdx.z;
    const float* X = Xg + (size_t)b * K * N;
    float*       Y = Yg + (size_t)b * M * N;

    __shared__ float As[8][128];
    __shared__ float Bsh[8][128];

    const int m0 = blockIdx.y * 128;
    const int n0 = blockIdx.x * 128;
    const int tid = threadIdx.x;
    const int tx = tid & 15;
    const int ty = tid >> 4;

    float acc[8][8];
    #pragma unroll
    for (int i = 0; i < 8; i++)
        #pragma unroll
        for (int j = 0; j < 8; j++) acc[i][j] = 0.f;

    for (int k0 = 0; k0 < K; k0 += 8) {
        {
            int row = tid >> 1;
            int kq  = (tid & 1) * 4;
            int m   = m0 + row;
            float4 a = make_float4(0.f, 0.f, 0.f, 0.f);
            if (m < M) a = *(const float4*)&Wm[(size_t)m * K + k0 + kq];
            As[kq+0][row] = a.x; As[kq+1][row] = a.y;
            As[kq+2][row] = a.z; As[kq+3][row] = a.w;
        }
        {
            int krow = tid >> 5;
            int nq   = (tid & 31) * 4;
            int n    = n0 + nq;
            float t0 = (n+0 < N) ? X[(size_t)(k0+krow)*N + n+0] : 0.f;
            float t1 = (n+1 < N) ? X[(size_t)(k0+krow)*N + n+1] : 0.f;
            float t2 = (n+2 < N) ? X[(size_t)(k0+krow)*N + n+2] : 0.f;
            float t3 = (n+3 < N) ? X[(size_t)(k0+krow)*N + n+3] : 0.f;
            *(float4*)&Bsh[krow][nq] = make_float4(t0, t1, t2, t3);
        }
        __syncthreads();
        #pragma unroll
        for (int kk = 0; kk < 8; kk++) {
            float a[8], bf[8];
            *(float4*)&a[0]  = *(const float4*)&As[kk][ty*8];
            *(float4*)&a[4]  = *(const float4*)&As[kk][ty*8 + 4];
            *(float4*)&bf[0] = *(const float4*)&Bsh[kk][tx*8];
            *(float4*)&bf[4] = *(const float4*)&Bsh[kk][tx*8 + 4];
            #pragma unroll
            for (int i = 0; i < 8; i++)
                #pragma unroll
                for (int j = 0; j < 8; j++)
                    acc[i][j] += a[i] * bf[j];
        }
        __syncthreads();
    }

    #pragma unroll
    for (int i = 0; i < 8; i++) {
        int m = m0 + ty*8 + i;
        if (m >= M) continue;
        float sc = bn[m] * rsqrtf(bn[3*M + m] + EPSV);
        float sh = bn[M + m] - bn[2*M + m] * sc;
        #pragma unroll
        for (int j = 0; j < 8; j++) {
            int n = n0 + tx*8 + j;
            if (n < N) {
                float v = acc[i][j] * sc + sh;
                Y[(size_t)m * N + n] = v > 0.f ? v : 0.f;
            }
        }
    }
}

// ---------------------------------------------------------------------------
// Attention (fp32, memory-bound); ctx output rounded to tf32 for wout GEMM.
// ---------------------------------------------------------------------------
__global__ void __launch_bounds__(256)
attn_k(const float* __restrict__ q, const float* __restrict__ kmat,
       const float* __restrict__ vmat, float* __restrict__ ctx)
{
    const int b  = blockIdx.y;
    const int n0 = blockIdx.x * 1024 + threadIdx.x * 4;

    __shared__ float ksh[CK_*KP_];
    __shared__ float vsh[CK_*KP_];
    for (int i = threadIdx.x; i < CK_*KP_; i += 256) {
        ksh[i] = kmat[b*CK_*KP_ + i];
        vsh[i] = vmat[b*CK_*KP_ + i];
    }
    __syncthreads();

    float sim[4][KP_];
    #pragma unroll
    for (int p = 0; p < 4; p++)
        #pragma unroll
        for (int t = 0; t < KP_; t++) sim[p][t] = 0.f;

    const float* qb = q + (size_t)b * CK_ * NPIX;
    for (int c = 0; c < CK_; c++) {
        float4 qv = *(const float4*)&qb[(size_t)c * NPIX + n0];
        #pragma unroll
        for (int t = 0; t < KP_; t++) {
            float kv = ksh[c*KP_ + t];
            sim[0][t] += qv.x * kv;
            sim[1][t] += qv.y * kv;
            sim[2][t] += qv.z * kv;
            sim[3][t] += qv.w * kv;
        }
    }

    #pragma unroll
    for (int p = 0; p < 4; p++) {
        float mx = -1e30f;
        #pragma unroll
        for (int t = 0; t < KP_; t++) { sim[p][t] *= 0.0625f; mx = fmaxf(mx, sim[p][t]); }
        float s = 0.f;
        #pragma unroll
        for (int t = 0; t < KP_; t++) { float e = __expf(sim[p][t] - mx); sim[p][t] = e; s += e; }
        float inv = 1.f / s;
        #pragma unroll
        for (int t = 0; t < KP_; t++) sim[p][t] *= inv;
    }

    float* cb = ctx + (size_t)b * CK_ * NPIX;
    for (int c = 0; c < CK_; c++) {
        float a0 = 0.f, a1 = 0.f, a2 = 0.f, a3 = 0.f;
        #pragma unroll
        for (int t = 0; t < KP_; t++) {
            float vv = vsh[c*KP_ + t];
            a0 += sim[0][t] * vv;
            a1 += sim[1][t] * vv;
            a2 += sim[2][t] * vv;
            a3 += sim[3][t] * vv;
        }
        *(float4*)&cb[(size_t)c * NPIX + n0] =
            make_float4(to_tf32(a0), to_tf32(a1), to_tf32(a2), to_tf32(a3));
    }
}

// ---------------------------------------------------------------------------
extern "C" void kernel_launch(void* const* d_in, const int* in_sizes, int n_in,
                              void* d_out, int out_size)
{
    const float *x, *proxy, *wq1, *wq2, *wk1, *wk2, *wv, *wout, *wbot;
    const float *bnq1, *bnq2, *bnk1, *bnk2, *bnv, *bnout, *bnbot;

    x     = (const float*)d_in[0];
    proxy = (const float*)d_in[1];
    if (in_sizes[3] == 1024 || in_sizes[3] == 2048) {
        wq1  = (const float*)d_in[2];  bnq1  = (const float*)d_in[3];
        wq2  = (const float*)d_in[4];  bnq2  = (const float*)d_in[5];
        wk1  = (const float*)d_in[6];  bnk1  = (const float*)d_in[7];
        wk2  = (const float*)d_in[8];  bnk2  = (const float*)d_in[9];
        wv   = (const float*)d_in[10]; bnv   = (const float*)d_in[11];
        wout = (const float*)d_in[12]; bnout = (const float*)d_in[13];
        wbot = (const float*)d_in[14]; bnbot = (const float*)d_in[15];
    } else {
        wq1  = (const float*)d_in[2];
        wq2  = (const float*)d_in[3];
        wk1  = (const float*)d_in[4];
        wk2  = (const float*)d_in[5];
        wv   = (const float*)d_in[6];
        wout = (const float*)d_in[7];
        wbot = (const float*)d_in[8];
        bnq1  = (const float*)d_in[9];
        bnq2  = (const float*)d_in[10];
        bnk1  = (const float*)d_in[11];
        bnk2  = (const float*)d_in[12];
        bnv   = (const float*)d_in[13];
        bnout = (const float*)d_in[14];
        bnbot = (const float*)d_in[15];
    }

    float *pq1, *pq, *pk1, *pk, *pv, *pctx, *pctxo;
    float *pxr, *pwq1r, *pwq2r, *pwoutr, *pwbotr;
    cudaGetSymbolAddress((void**)&pq1,   g_q1);
    cudaGetSymbolAddress((void**)&pq,    g_q);
    cudaGetSymbolAddress((void**)&pk1,   g_k1);
    cudaGetSymbolAddress((void**)&pk,    g_k);
    cudaGetSymbolAddress((void**)&pv,    g_v);
    cudaGetSymbolAddress((void**)&pctx,  g_ctx);
    cudaGetSymbolAddress((void**)&pctxo, g_ctxo);
    cudaGetSymbolAddress((void**)&pxr,   g_xr);
    cudaGetSymbolAddress((void**)&pwq1r, g_wq1r);
    cudaGetSymbolAddress((void**)&pwq2r, g_wq2r);
    cudaGetSymbolAddress((void**)&pwoutr, g_woutr);
    cudaGetSymbolAddress((void**)&pwbotr, g_wbotr);

    float* out = (float*)d_out;

    // tf32 rounding prepass (x + the 4 big weights)
    {
        int n4;
        n4 = (B_*C_*NPIX)/4;  round_k<<<(n4+255)/256, 256>>>(x,    pxr,    n4);
        n4 = (CK_*C_)/4;      round_k<<<(n4+255)/256, 256>>>(wq1,  pwq1r,  n4);
        n4 = (CK_*CK_)/4;     round_k<<<(n4+255)/256, 256>>>(wq2,  pwq2r,  n4);
        n4 = (C_*CK_)/4;      round_k<<<(n4+255)/256, 256>>>(wout, pwoutr, n4);
        n4 = (CO_*KCONV)/4;   round_k<<<(n4+255)/256, 256>>>(wbot, pwbotr, n4);
    }

    // q path (tf32 tensor cores): x_r -> q1 -> q
    mma_gemm_k<false><<<dim3(NPIX/128, CK_/128, B_), 256>>>(
        pwq1r, pxr, nullptr, bnq1, pq1, C_,  CK_, 1);
    mma_gemm_k<false><<<dim3(NPIX/128, CK_/128, B_), 256>>>(
        pwq2r, pq1, nullptr, bnq2, pq,  CK_, CK_, 1);

    // k/v path (fp32, tiny)
    gemm_bn_relu_k<<<dim3(1, 2, B_), 256>>>(wk1, proxy, bnk1, pk1, CK_, C_,  KP_);
    gemm_bn_relu_k<<<dim3(1, 2, B_), 256>>>(wk2, pk1,   bnk2, pk,  CK_, CK_, KP_);
    gemm_bn_relu_k<<<dim3(1, 2, B_), 256>>>(wv,  proxy, bnv,  pv,  CK_, C_,  KP_);

    // attention -> ctx (tf32-rounded output)
    attn_k<<<dim3(NPIX/1024, B_), 256>>>(pq, pk, pv, pctx);

    // wout (tf32): ctx -> ctxo (rounded for conv)
    mma_gemm_k<false><<<dim3(NPIX/128, C_/128, B_), 256>>>(
        pwoutr, pctx, nullptr, bnout, pctxo, CK_, C_, 1);

    // 3x3 conv over virtual concat [ctxo ; x_r] (tf32 tensor cores)
    mma_gemm_k<true><<<dim3(NPIX/128, CO_/128, B_), 256>>>(
        pwbotr, pctxo, pxr, bnbot, out, KCONV, CO_, 0);
}

// round 7
// speedup vs baseline: 3.1372x; 1.3060x over previous
#include <cuda_runtime.h>
#include <math.h>
#include <stdint.h>

#define EPSV 1e-5f

#define B_   2
#define C_   512
#define H_   128
#define W_   256
#define NPIX (H_*W_)        // 32768
#define CK_  256
#define KP_  19
#define CO_  512
#define KCONV (1024*9)      // 9216

// ---------------- scratch (device globals; no allocation allowed) ----------
__device__ float g_q1  [B_*CK_*NPIX];
__device__ float g_q   [B_*CK_*NPIX];
__device__ float g_k1  [B_*CK_*KP_];
__device__ float g_k   [B_*CK_*KP_];
__device__ float g_v   [B_*CK_*KP_];
__device__ float g_ctx [B_*CK_*NPIX];
__device__ float g_ctxo[B_*C_*NPIX];
__device__ float g_xr  [B_*C_*NPIX];     // x rounded to tf32
__device__ float g_wq1r [CK_*C_];        // rounded + k-permuted
__device__ float g_wq2r [CK_*CK_];
__device__ float g_woutr[C_*CK_];
__device__ float g_wbotr[CO_*KCONV];

// ---------------- helpers --------------------------------------------------
__device__ __forceinline__ float to_tf32(float x) {
    uint32_t r; asm("cvt.rna.tf32.f32 %0, %1;" : "=r"(r) : "f"(x));
    return __uint_as_float(r);
}
__device__ __forceinline__ uint32_t saddr(const void* p) {
    return (uint32_t)__cvta_generic_to_shared(p);
}
__device__ __forceinline__ void cp16(uint32_t dst, const void* src) {
    asm volatile("cp.async.cg.shared.global [%0], [%1], 16;\n" :: "r"(dst), "l"(src));
}
__device__ __forceinline__ void mma_tf32(float* d, const uint32_t* a, const uint32_t* b) {
    asm volatile(
        "mma.sync.aligned.m16n8k8.row.col.f32.tf32.tf32.f32 "
        "{%0,%1,%2,%3}, {%4,%5,%6,%7}, {%8,%9}, {%0,%1,%2,%3};\n"
        : "+f"(d[0]), "+f"(d[1]), "+f"(d[2]), "+f"(d[3])
        : "r"(a[0]), "r"(a[1]), "r"(a[2]), "r"(a[3]), "r"(b[0]), "r"(b[1]));
}

// round-to-tf32 prepass (float4 vectorized; n divisible by 4)
__global__ void round_k(const float* __restrict__ s, float* __restrict__ d, int n4) {
    int i = blockIdx.x * 256 + threadIdx.x;
    if (i < n4) {
        float4 v = ((const float4*)s)[i];
        v.x = to_tf32(v.x); v.y = to_tf32(v.y); v.z = to_tf32(v.z); v.w = to_tf32(v.w);
        ((float4*)d)[i] = v;
    }
}

// round + permute weights: out[m][kb*16 + pos(k)] = tf32(in[m][kb*16 + k])
// pos(k) = (k>>3)*8 + (k&3)*2 + ((k>>2)&1)  (pairs (k, k+4) adjacent)
__global__ void round_perm_k(const float* __restrict__ s, float* __restrict__ d,
                             int total, int K) {
    int i = blockIdx.x * 256 + threadIdx.x;
    if (i < total) {
        int m  = i / K;
        int kk = i - m * K;
        int kb = kk >> 4;
        int k  = kk & 15;
        int pos = ((k >> 3) << 3) + ((k & 3) << 1) + ((k >> 2) & 1);
        d[(size_t)m * K + (kb << 4) + pos] = to_tf32(s[i]);
    }
}

// ---------------------------------------------------------------------------
// tf32 tensor-core GEMM / implicit-conv kernel.
//   Y[b](Mtot, NPIX) = relu(bn( A(Mtot,K) * B[b](K, NPIX) ))
// CONV: B is implicit im2col of [Xg(ctxo) ; X2g(x)], 3x3 SAME; kx applied at
//       fragment-read time from an unshifted halo row.
// Block tile 256x128, 512 thr (16 warps, warp tile 64x32), BK=16,
// 2-stage cp.async (16B vectors only). Dynamic smem 66560 B.
//   As[st][m 0..255][24]  (k-permuted pairs; frag = LDS.64)
//   Bs[st][k 0..15][136]  (cols 4..131 = pixels n0..n0+127; 4-col halo)
// ---------------------------------------------------------------------------
#define ASTRIDE 24
#define BW 136
#define AS_ST (256*ASTRIDE)      // 6144 floats per stage
#define BS_ST (16*BW)            // 2176 floats per stage
#define SMEM_FLOATS (2*AS_ST + 2*BS_ST)

template<bool CONV>
__global__ void __launch_bounds__(512, 1)
mma_gemm_k(const float* __restrict__ Ap, const float* __restrict__ Xg,
           const float* __restrict__ X2g, const float* __restrict__ bn,
           float* __restrict__ Yg, int K, int Mtot, int round_out)
{
    extern __shared__ float sm[];
    float* Asm = sm;                 // [2][256][24]
    float* Bsm = sm + 2 * AS_ST;     // [2][16][136]

    const int b    = blockIdx.z;
    const int m0   = blockIdx.x * 256;
    const int n0   = blockIdx.y * 128;
    const int tid  = threadIdx.x;
    const int lane = tid & 31;
    const int wid  = tid >> 5;
    const int wm   = wid & 3;   // 4 warps along M
    const int wn   = wid >> 2;  // 4 warps along N

    const int y0 = n0 >> 8;     // image row of all 128 pixels (W_=256)
    const int x0 = n0 & 255;    // 0 or 128

    const float* Xb  = CONV ? (Xg  + (size_t)b * C_ * NPIX) : (Xg + (size_t)b * K * NPIX);
    const float* X2b = CONV ? (X2g + (size_t)b * C_ * NPIX) : nullptr;
    float*       Yb  = Yg + (size_t)b * Mtot * NPIX;

    float acc[4][4][4];
    #pragma unroll
    for (int i = 0; i < 4; i++)
        #pragma unroll
        for (int j = 0; j < 4; j++)
            #pragma unroll
            for (int r = 0; r < 4; r++) acc[i][j][r] = 0.f;

    const int nkb = K / 16;

    auto stage = [&](int st, int kb) {
        const int k0 = kb * 16;
        // ---- A tile: 256 m x 16 k; gmem is pre-permuted -> direct 16B copies
        float* As = Asm + st * AS_ST;
        #pragma unroll
        for (int rep = 0; rep < 2; rep++) {
            int v = tid + rep * 512;        // 0..1023
            int m = v >> 2;
            int q = (v & 3) << 2;
            cp16(saddr(&As[m * ASTRIDE + q]), &Ap[(size_t)(m0 + m) * K + k0 + q]);
        }
        // ---- B tile: 16 k-rows x 136 cols (halo). 544 vectors.
        float* Bs = Bsm + st * BS_ST;
        for (int v = tid; v < 16 * 34; v += 512) {
            int krow = v / 34;
            int j    = v - krow * 34;
            float* dst = &Bs[krow * BW + j * 4];
            if (CONV) {
                int kg  = k0 + krow;
                int ic  = kg / 9;
                int tap = kg - ic * 9;
                int ky  = tap / 3 - 1;
                int yy  = y0 + ky;
                int gx  = x0 + j * 4 - 4;
                if (yy >= 0 && yy < H_ && gx >= 0 && gx < W_) {
                    const float* src = (ic < C_) ? (Xb + (size_t)ic * NPIX)
                                                 : (X2b + (size_t)(ic - C_) * NPIX);
                    cp16(saddr(dst), &src[yy * W_ + gx]);
                } else {
                    *(float4*)dst = make_float4(0.f, 0.f, 0.f, 0.f);
                }
            } else {
                if (j >= 1 && j <= 32)
                    cp16(saddr(dst), &Xb[(size_t)(k0 + krow) * NPIX + n0 + j * 4 - 4]);
            }
        }
    };

    auto domma = [&](int st, int k0g) {
        const float* As = Asm + st * AS_ST;
        const float* Bs = Bsm + st * BS_ST;
        #pragma unroll
        for (int s = 0; s < 2; s++) {
            const int co = s * 8 + ((lane & 3) << 1);
            uint32_t a[4][4], bb[4][2];
            #pragma unroll
            for (int mt = 0; mt < 4; mt++) {
                int r = wm * 64 + mt * 16 + (lane >> 2);
                float2 t0 = *(const float2*)&As[r * ASTRIDE + co];
                float2 t1 = *(const float2*)&As[(r + 8) * ASTRIDE + co];
                a[mt][0] = __float_as_uint(t0.x);
                a[mt][2] = __float_as_uint(t0.y);
                a[mt][1] = __float_as_uint(t1.x);
                a[mt][3] = __float_as_uint(t1.y);
            }
            const int kA = s * 8 + (lane & 3);
            const int kB = kA + 4;
            int oA = 4, oB = 4;
            if (CONV) {
                int tA = (k0g + kA) % 9;
                int tB = (k0g + kB) % 9;
                oA = 4 + (tA - (tA / 3) * 3) - 1;   // 4 + kx
                oB = 4 + (tB - (tB / 3) * 3) - 1;
            }
            const float* rowA = &Bs[kA * BW + oA];
            const float* rowB = &Bs[kB * BW + oB];
            #pragma unroll
            for (int nt = 0; nt < 4; nt++) {
                int nn = wn * 32 + nt * 8 + (lane >> 2);
                bb[nt][0] = __float_as_uint(rowA[nn]);
                bb[nt][1] = __float_as_uint(rowB[nn]);
            }
            #pragma unroll
            for (int mt = 0; mt < 4; mt++)
                #pragma unroll
                for (int nt = 0; nt < 4; nt++)
                    mma_tf32(acc[mt][nt], a[mt], bb[nt]);
        }
    };

    stage(0, 0);
    asm volatile("cp.async.commit_group;\n");

    for (int kb = 0; kb < nkb; kb++) {
        if (kb + 1 < nkb) {
            stage((kb + 1) & 1, kb + 1);
            asm volatile("cp.async.commit_group;\n");
            asm volatile("cp.async.wait_group 1;\n");
        } else {
            asm volatile("cp.async.wait_group 0;\n");
        }
        __syncthreads();
        domma(kb & 1, kb * 16);
        __syncthreads();
    }

    // epilogue: BN + ReLU (+ optional tf32 rounding), float2 stores
    #pragma unroll
    for (int mt = 0; mt < 4; mt++) {
        int mr = m0 + wm * 64 + mt * 16 + (lane >> 2);
        #pragma unroll
        for (int half = 0; half < 2; half++) {
            int m = mr + half * 8;
            float sc = bn[m] * rsqrtf(bn[3 * Mtot + m] + EPSV);
            float sh = bn[Mtot + m] - bn[2 * Mtot + m] * sc;
            #pragma unroll
            for (int nt = 0; nt < 4; nt++) {
                int n = n0 + wn * 32 + nt * 8 + ((lane & 3) << 1);
                float v0 = acc[mt][nt][half * 2 + 0] * sc + sh;
                float v1 = acc[mt][nt][half * 2 + 1] * sc + sh;
                v0 = v0 > 0.f ? v0 : 0.f;
                v1 = v1 > 0.f ? v1 : 0.f;
                if (round_out) { v0 = to_tf32(v0); v1 = to_tf32(v1); }
                *(float2*)&Yb[(size_t)m * NPIX + n] = make_float2(v0, v1);
            }
        }
    }
}

// ---------------------------------------------------------------------------
// fp32 GEMM+BN+ReLU (tiny N=19 k/v-path GEMMs only)
// ---------------------------------------------------------------------------
__global__ void __launch_bounds__(256)
gemm_bn_relu_k(const float* __restrict__ Wm, const float* __restrict__ Xg,
               const float* __restrict__ bn, float* __restrict__ Yg,
               int M, int K, int N)
{
    const int b = blockIdx.z;
    const float* X = Xg + (size_t)b * K * N;
    float*       Y = Yg + (size_t)b * M * N;

    __shared__ float As[8][128];
    __shared__ float Bsh[8][128];

    const int m0 = blockIdx.y * 128;
    const int n0 = blockIdx.x * 128;
    const int tid = threadIdx.x;
    const int tx = tid & 15;
    const int ty = tid >> 4;

    float acc[8][8];
    #pragma unroll
    for (int i = 0; i < 8; i++)
        #pragma unroll
        for (int j = 0; j < 8; j++) acc[i][j] = 0.f;

    for (int k0 = 0; k0 < K; k0 += 8) {
        {
            int row = tid >> 1;
            int kq  = (tid & 1) * 4;
            int m   = m0 + row;
            float4 a = make_float4(0.f, 0.f, 0.f, 0.f);
            if (m < M) a = *(const float4*)&Wm[(size_t)m * K + k0 + kq];
            As[kq+0][row] = a.x; As[kq+1][row] = a.y;
            As[kq+2][row] = a.z; As[kq+3][row] = a.w;
        }
        {
            int krow = tid >> 5;
            int nq   = (tid & 31) * 4;
            int n    = n0 + nq;
            float t0 = (n+0 < N) ? X[(size_t)(k0+krow)*N + n+0] : 0.f;
            float t1 = (n+1 < N) ? X[(size_t)(k0+krow)*N + n+1] : 0.f;
            float t2 = (n+2 < N) ? X[(size_t)(k0+krow)*N + n+2] : 0.f;
            float t3 = (n+3 < N) ? X[(size_t)(k0+krow)*N + n+3] : 0.f;
            *(float4*)&Bsh[krow][nq] = make_float4(t0, t1, t2, t3);
        }
        __syncthreads();
        #pragma unroll
        for (int kk = 0; kk < 8; kk++) {
            float a[8], bf[8];
            *(float4*)&a[0]  = *(const float4*)&As[kk][ty*8];
            *(float4*)&a[4]  = *(const float4*)&As[kk][ty*8 + 4];
            *(float4*)&bf[0] = *(const float4*)&Bsh[kk][tx*8];
            *(float4*)&bf[4] = *(const float4*)&Bsh[kk][tx*8 + 4];
            #pragma unroll
            for (int i = 0; i < 8; i++)
                #pragma unroll
                for (int j = 0; j < 8; j++)
                    acc[i][j] += a[i] * bf[j];
        }
        __syncthreads();
    }

    #pragma unroll
    for (int i = 0; i < 8; i++) {
        int m = m0 + ty*8 + i;
        if (m >= M) continue;
        float sc = bn[m] * rsqrtf(bn[3*M + m] + EPSV);
        float sh = bn[M + m] - bn[2*M + m] * sc;
        #pragma unroll
        for (int j = 0; j < 8; j++) {
            int n = n0 + tx*8 + j;
            if (n < N) {
                float v = acc[i][j] * sc + sh;
                Y[(size_t)m * N + n] = v > 0.f ? v : 0.f;
            }
        }
    }
}

// ---------------------------------------------------------------------------
// Attention (fp32, memory-bound); ctx output rounded to tf32 for wout GEMM.
// ---------------------------------------------------------------------------
__global__ void __launch_bounds__(256)
attn_k(const float* __restrict__ q, const float* __restrict__ kmat,
       const float* __restrict__ vmat, float* __restrict__ ctx)
{
    const int b  = blockIdx.y;
    const int n0 = blockIdx.x * 1024 + threadIdx.x * 4;

    __shared__ float ksh[CK_*KP_];
    __shared__ float vsh[CK_*KP_];
    for (int i = threadIdx.x; i < CK_*KP_; i += 256) {
        ksh[i] = kmat[b*CK_*KP_ + i];
        vsh[i] = vmat[b*CK_*KP_ + i];
    }
    __syncthreads();

    float sim[4][KP_];
    #pragma unroll
    for (int p = 0; p < 4; p++)
        #pragma unroll
        for (int t = 0; t < KP_; t++) sim[p][t] = 0.f;

    const float* qb = q + (size_t)b * CK_ * NPIX;
    for (int c = 0; c < CK_; c++) {
        float4 qv = *(const float4*)&qb[(size_t)c * NPIX + n0];
        #pragma unroll
        for (int t = 0; t < KP_; t++) {
            float kv = ksh[c*KP_ + t];
            sim[0][t] += qv.x * kv;
            sim[1][t] += qv.y * kv;
            sim[2][t] += qv.z * kv;
            sim[3][t] += qv.w * kv;
        }
    }

    #pragma unroll
    for (int p = 0; p < 4; p++) {
        float mx = -1e30f;
        #pragma unroll
        for (int t = 0; t < KP_; t++) { sim[p][t] *= 0.0625f; mx = fmaxf(mx, sim[p][t]); }
        float s = 0.f;
        #pragma unroll
        for (int t = 0; t < KP_; t++) { float e = __expf(sim[p][t] - mx); sim[p][t] = e; s += e; }
        float inv = 1.f / s;
        #pragma unroll
        for (int t = 0; t < KP_; t++) sim[p][t] *= inv;
    }

    float* cb = ctx + (size_t)b * CK_ * NPIX;
    for (int c = 0; c < CK_; c++) {
        float a0 = 0.f, a1 = 0.f, a2 = 0.f, a3 = 0.f;
        #pragma unroll
        for (int t = 0; t < KP_; t++) {
            float vv = vsh[c*KP_ + t];
            a0 += sim[0][t] * vv;
            a1 += sim[1][t] * vv;
            a2 += sim[2][t] * vv;
            a3 += sim[3][t] * vv;
        }
        *(float4*)&cb[(size_t)c * NPIX + n0] =
            make_float4(to_tf32(a0), to_tf32(a1), to_tf32(a2), to_tf32(a3));
    }
}

// ---------------------------------------------------------------------------
extern "C" void kernel_launch(void* const* d_in, const int* in_sizes, int n_in,
                              void* d_out, int out_size)
{
    const float *x, *proxy, *wq1, *wq2, *wk1, *wk2, *wv, *wout, *wbot;
    const float *bnq1, *bnq2, *bnk1, *bnk2, *bnv, *bnout, *bnbot;

    x     = (const float*)d_in[0];
    proxy = (const float*)d_in[1];
    if (in_sizes[3] == 1024 || in_sizes[3] == 2048) {
        wq1  = (const float*)d_in[2];  bnq1  = (const float*)d_in[3];
        wq2  = (const float*)d_in[4];  bnq2  = (const float*)d_in[5];
        wk1  = (const float*)d_in[6];  bnk1  = (const float*)d_in[7];
        wk2  = (const float*)d_in[8];  bnk2  = (const float*)d_in[9];
        wv   = (const float*)d_in[10]; bnv   = (const float*)d_in[11];
        wout = (const float*)d_in[12]; bnout = (const float*)d_in[13];
        wbot = (const float*)d_in[14]; bnbot = (const float*)d_in[15];
    } else {
        wq1  = (const float*)d_in[2];
        wq2  = (const float*)d_in[3];
        wk1  = (const float*)d_in[4];
        wk2  = (const float*)d_in[5];
        wv   = (const float*)d_in[6];
        wout = (const float*)d_in[7];
        wbot = (const float*)d_in[8];
        bnq1  = (const float*)d_in[9];
        bnq2  = (const float*)d_in[10];
        bnk1  = (const float*)d_in[11];
        bnk2  = (const float*)d_in[12];
        bnv   = (const float*)d_in[13];
        bnout = (const float*)d_in[14];
        bnbot = (const float*)d_in[15];
    }

    float *pq1, *pq, *pk1, *pk, *pv, *pctx, *pctxo;
    float *pxr, *pwq1r, *pwq2r, *pwoutr, *pwbotr;
    cudaGetSymbolAddress((void**)&pq1,   g_q1);
    cudaGetSymbolAddress((void**)&pq,    g_q);
    cudaGetSymbolAddress((void**)&pk1,   g_k1);
    cudaGetSymbolAddress((void**)&pk,    g_k);
    cudaGetSymbolAddress((void**)&pv,    g_v);
    cudaGetSymbolAddress((void**)&pctx,  g_ctx);
    cudaGetSymbolAddress((void**)&pctxo, g_ctxo);
    cudaGetSymbolAddress((void**)&pxr,   g_xr);
    cudaGetSymbolAddress((void**)&pwq1r, g_wq1r);
    cudaGetSymbolAddress((void**)&pwq2r, g_wq2r);
    cudaGetSymbolAddress((void**)&pwoutr, g_woutr);
    cudaGetSymbolAddress((void**)&pwbotr, g_wbotr);

    float* out = (float*)d_out;

    const int SMEM_BYTES = SMEM_FLOATS * 4;   // 66560
    cudaFuncSetAttribute(mma_gemm_k<false>,
                         cudaFuncAttributeMaxDynamicSharedMemorySize, SMEM_BYTES);
    cudaFuncSetAttribute(mma_gemm_k<true>,
                         cudaFuncAttributeMaxDynamicSharedMemorySize, SMEM_BYTES);

    // prepass: round x; round+permute the 4 tensor-core weights
    {
        int n4 = (B_*C_*NPIX)/4;
        round_k<<<(n4+255)/256, 256>>>(x, pxr, n4);
        int t;
        t = CK_*C_;    round_perm_k<<<(t+255)/256, 256>>>(wq1,  pwq1r,  t, C_);
        t = CK_*CK_;   round_perm_k<<<(t+255)/256, 256>>>(wq2,  pwq2r,  t, CK_);
        t = C_*CK_;    round_perm_k<<<(t+255)/256, 256>>>(wout, pwoutr, t, CK_);
        t = CO_*KCONV; round_perm_k<<<(t+255)/256, 256>>>(wbot, pwbotr, t, KCONV);
    }

    // q path (tf32): x_r -> q1 -> q   (M=256 -> one m-block)
    mma_gemm_k<false><<<dim3(1, NPIX/128, B_), 512, SMEM_BYTES>>>(
        pwq1r, pxr, nullptr, bnq1, pq1, C_,  CK_, 1);
    mma_gemm_k<false><<<dim3(1, NPIX/128, B_), 512, SMEM_BYTES>>>(
        pwq2r, pq1, nullptr, bnq2, pq,  CK_, CK_, 1);

    // k/v path (fp32, tiny)
    gemm_bn_relu_k<<<dim3(1, 2, B_), 256>>>(wk1, proxy, bnk1, pk1, CK_, C_,  KP_);
    gemm_bn_relu_k<<<dim3(1, 2, B_), 256>>>(wk2, pk1,   bnk2, pk,  CK_, CK_, KP_);
    gemm_bn_relu_k<<<dim3(1, 2, B_), 256>>>(wv,  proxy, bnv,  pv,  CK_, C_,  KP_);

    // attention -> ctx (tf32-rounded output)
    attn_k<<<dim3(NPIX/1024, B_), 256>>>(pq, pk, pv, pctx);

    // wout (tf32): ctx -> ctxo (M=512 -> 2 m-blocks)
    mma_gemm_k<false><<<dim3(2, NPIX/128, B_), 512, SMEM_BYTES>>>(
        pwoutr, pctx, nullptr, bnout, pctxo, CK_, C_, 1);

    // 3x3 conv over virtual concat [ctxo ; x_r]
    mma_gemm_k<true><<<dim3(2, NPIX/128, B_), 512, SMEM_BYTES>>>(
        pwbotr, pctxo, pxr, bnbot, out, KCONV, CO_, 0);
}